// round 5
// baseline (speedup 1.0000x reference)
#include <cuda_runtime.h>
#include <math.h>

#define NN 100000
#define NE 1600000
#define DD 512
#define HH 256
#define KK 64

// Scratch: __device__ globals, referenced ONLY from device code.
__device__ float4 g_hw4[(size_t)NN * HH / 4];   // GEMM output (message source)
__device__ float4 g_h4 [(size_t)NN * HH / 4];   // aggregated hidden state
__device__ float  g_dinv[NN];                   // deg -> rsqrt(deg)
__device__ int    g_is64;                       // edge_index dtype flag

// ---------------------------------------------------------------------------
// Edge dtype detection: int64 values < 2^31 have zero high words at odd int32
// slots; random int32 indices do not. Reads only first 128 ints (in-bounds
// under both layouts).
// ---------------------------------------------------------------------------
__global__ void k_detect(const int* ei_raw) {
    if (threadIdx.x == 0 && blockIdx.x == 0) {
        int all0 = 1;
        for (int i = 0; i < 64; i++)
            if (ei_raw[2 * i + 1] != 0) { all0 = 0; break; }
        g_is64 = all0;
    }
}

__device__ __forceinline__ int edge_at(const int* ei_raw, size_t idx) {
    // little-endian: low word of int64 element idx sits at raw[2*idx]
    return g_is64 ? ei_raw[2 * idx] : ei_raw[idx];
}

// ---------------------------------------------------------------------------
// Degree / normalization
// ---------------------------------------------------------------------------
__global__ void k_deg_init() {
    int i = blockIdx.x * blockDim.x + threadIdx.x;
    if (i < NN) g_dinv[i] = 1.0f;          // self-loop contributes 1
}

__global__ void k_deg_count(const int* ei_raw) {
    int e = blockIdx.x * blockDim.x + threadIdx.x;
    if (e >= NE) return;
    int d = edge_at(ei_raw, (size_t)NE + e);       // dst row
    if (d >= 0 && d < NN) atomicAdd(&g_dinv[d], 1.0f);
}

__global__ void k_dinv() {
    int i = blockIdx.x * blockDim.x + threadIdx.x;
    if (i < NN) g_dinv[i] = rsqrtf(g_dinv[i]);   // deg >= 1 always
}

// ---------------------------------------------------------------------------
// Tiled SGEMM: C[M,Nc] = op(A)[M,Kc] @ B[Kc,Nc].
// A_SRC: 0 = external arg, 1 = g_h.   C_DST: 0 = external arg, 1 = g_hw.
// BM=128, BN=64, BK=16, TM=8, TN=4, 256 threads.
// ---------------------------------------------------------------------------
template<bool RELU_A, int A_SRC, int C_DST>
__global__ void k_sgemm(const float* Aext, const float* B, float* Cext,
                        int M, int Kc, int Nc) {
    const float* A = (A_SRC == 1) ? (const float*)g_h4 : Aext;
    float*       C = (C_DST == 1) ? (float*)g_hw4      : Cext;

    const int BM = 128, BN = 64, BK = 16, TM = 8, TN = 4;
    __shared__ float As[BK][BM];   // transposed A tile
    __shared__ float Bs[BK][BN];

    int tid  = threadIdx.x;
    int brow = blockIdx.y * BM;
    int bcol = blockIdx.x * BN;
    int tcol = tid & 15;           // 16 thread-cols * TN=4 -> 64
    int trow = tid >> 4;           // 16 thread-rows * TM=8 -> 128

    float acc[TM][TN];
    #pragma unroll
    for (int m = 0; m < TM; m++)
        #pragma unroll
        for (int n = 0; n < TN; n++) acc[m][n] = 0.0f;

    for (int k0 = 0; k0 < Kc; k0 += BK) {
        #pragma unroll
        for (int l = 0; l < 2; l++) {
            int f  = tid + l * 256;
            int ar = f >> 2;              // 0..127
            int ak = (f & 3) << 2;        // 0,4,8,12
            int gr = brow + ar;
            float4 v = make_float4(0.f, 0.f, 0.f, 0.f);
            if (gr < M) v = *(const float4*)(A + (size_t)gr * Kc + k0 + ak);
            if (RELU_A) {
                v.x = fmaxf(v.x, 0.f); v.y = fmaxf(v.y, 0.f);
                v.z = fmaxf(v.z, 0.f); v.w = fmaxf(v.w, 0.f);
            }
            As[ak + 0][ar] = v.x;
            As[ak + 1][ar] = v.y;
            As[ak + 2][ar] = v.z;
            As[ak + 3][ar] = v.w;
        }
        {
            int br = tid >> 4;            // 0..15
            int bc = (tid & 15) << 2;     // 0..60
            *(float4*)&Bs[br][bc] =
                *(const float4*)(B + (size_t)(k0 + br) * Nc + bcol + bc);
        }
        __syncthreads();

        #pragma unroll
        for (int k = 0; k < BK; k++) {
            float af[TM], bf[TN];
            #pragma unroll
            for (int m = 0; m < TM; m++) af[m] = As[k][trow * TM + m];
            #pragma unroll
            for (int n = 0; n < TN; n++) bf[n] = Bs[k][tcol * TN + n];
            #pragma unroll
            for (int m = 0; m < TM; m++)
                #pragma unroll
                for (int n = 0; n < TN; n++)
                    acc[m][n] = fmaf(af[m], bf[n], acc[m][n]);
        }
        __syncthreads();
    }

    #pragma unroll
    for (int m = 0; m < TM; m++) {
        int gr = brow + trow * TM + m;
        if (gr < M) {
            float4 v = make_float4(acc[m][0], acc[m][1], acc[m][2], acc[m][3]);
            *(float4*)(C + (size_t)gr * Nc + bcol + tcol * TN) = v;
        }
    }
}

// ---------------------------------------------------------------------------
// Aggregation init: g_h[i] = bias + dinv[row]^2 * g_hw[i]  (self-loop + bias)
// ---------------------------------------------------------------------------
__global__ void k_agg_init(const float* bias) {
    int idx = blockIdx.x * blockDim.x + threadIdx.x;      // float4 index
    const int TOT = NN * (HH / 4);
    if (idx >= TOT) return;
    int row = idx / (HH / 4);
    int j4  = idx - row * (HH / 4);
    float di = g_dinv[row];
    float w  = di * di;
    float4 h = g_hw4[idx];
    float4 b = ((const float4*)bias)[j4];
    float4 o = make_float4(fmaf(w, h.x, b.x), fmaf(w, h.y, b.y),
                           fmaf(w, h.z, b.z), fmaf(w, h.w, b.w));
    g_h4[idx] = o;
}

// Edge scatter: one warp per edge, g_h[dst] += norm * g_hw[src]
__global__ void k_agg_edge(const int* ei_raw) {
    int gtid = blockIdx.x * blockDim.x + threadIdx.x;
    int e    = gtid >> 5;
    int lane = gtid & 31;
    if (e >= NE) return;
    int s = edge_at(ei_raw, (size_t)e);
    int d = edge_at(ei_raw, (size_t)NE + e);
    if ((unsigned)s >= NN || (unsigned)d >= NN) return;
    float w = g_dinv[s] * g_dinv[d];
    const float4* hs4 = g_hw4 + (size_t)s * (HH / 4);
    float*        od  = (float*)g_h4 + (size_t)d * HH;
    #pragma unroll
    for (int jj = 0; jj < 2; jj++) {
        int j4 = lane + jj * 32;          // 0..63 float4 slots
        float4 v = hs4[j4];
        int j = j4 * 4;
        atomicAdd(od + j + 0, w * v.x);
        atomicAdd(od + j + 1, w * v.y);
        atomicAdd(od + j + 2, w * v.z);
        atomicAdd(od + j + 3, w * v.w);
    }
}

// ---------------------------------------------------------------------------
// Softmax over K=64, warp per row. d_out layout: [S | logits], each NN*KK.
// ---------------------------------------------------------------------------
__global__ void k_softmax(const float* log_tau, float* out) {
    int gtid = blockIdx.x * blockDim.x + threadIdx.x;
    int row  = gtid >> 5;
    int lane = gtid & 31;
    if (row >= NN) return;
    const float* lg = out + (size_t)NN * KK + (size_t)row * KK;
    float inv_tau = __expf(-log_tau[0]);
    float a = lg[lane] * inv_tau;
    float b = lg[lane + 32] * inv_tau;
    float m = fmaxf(a, b);
    #pragma unroll
    for (int off = 16; off > 0; off >>= 1)
        m = fmaxf(m, __shfl_xor_sync(0xFFFFFFFFu, m, off));
    float e0 = __expf(a - m);
    float e1 = __expf(b - m);
    float s = e0 + e1;
    #pragma unroll
    for (int off = 16; off > 0; off >>= 1)
        s += __shfl_xor_sync(0xFFFFFFFFu, s, off);
    float inv = 1.0f / s;
    float* S = out + (size_t)row * KK;
    S[lane]      = e0 * inv;
    S[lane + 32] = e1 * inv;
}

// ---------------------------------------------------------------------------
extern "C" void kernel_launch(void* const* d_in, const int* in_sizes, int n_in,
                              void* d_out, int out_size) {
    const float* x       = (const float*)d_in[0];
    const int*   ei_raw  = (const int*)d_in[1];    // int32 OR int64 (detected)
    const float* W1      = (const float*)d_in[2];
    const float* b1      = (const float*)d_in[3];
    const float* W2      = (const float*)d_in[4];
    const float* b2      = (const float*)d_in[5];
    const float* Wk      = (const float*)d_in[6];
    const float* log_tau = (const float*)d_in[7];
    float* out = (float*)d_out;

    // dtype detection + norms
    k_detect   <<<1, 32>>>(ei_raw);
    k_deg_init <<<(NN + 255) / 256, 256>>>();
    k_deg_count<<<(NE + 255) / 256, 256>>>(ei_raw);
    k_dinv     <<<(NN + 255) / 256, 256>>>();

    dim3 gemm_grid_H(HH / 64, (NN + 127) / 128);
    dim3 gemm_grid_K(KK / 64, (NN + 127) / 128);

    // Layer 1: g_hw = x @ W1 ; g_h = b1 + selfloop + edge scatter
    k_sgemm<false, 0, 1><<<gemm_grid_H, 256>>>(x, W1, nullptr, NN, DD, HH);
    k_agg_init<<<(NN * (HH / 4) + 255) / 256, 256>>>(b1);
    k_agg_edge<<<NE / 8, 256>>>(ei_raw);

    // Layer 2: g_hw = relu(g_h) @ W2 ; g_h = b2 + selfloop + edge scatter
    k_sgemm<true, 1, 1><<<gemm_grid_H, 256>>>(nullptr, W2, nullptr, NN, HH, HH);
    k_agg_init<<<(NN * (HH / 4) + 255) / 256, 256>>>(b2);
    k_agg_edge<<<NE / 8, 256>>>(ei_raw);

    // Head: logits = g_h @ Wk ; S = softmax(logits / tau)
    float* logits = out + (size_t)NN * KK;
    k_sgemm<false, 1, 0><<<gemm_grid_K, 256>>>(nullptr, Wk, logits, NN, HH, KK);
    k_softmax<<<(NN + 7) / 8, 256>>>(log_tau, out);
}

// round 9
// speedup vs baseline: 1.0907x; 1.0907x over previous
#include <cuda_runtime.h>
#include <cuda_bf16.h>
#include <math.h>

#define NN 100000
#define NE 1600000
#define DD 512
#define HH 256
#define KK 64

// Scratch: __device__ globals, referenced ONLY from device code.
__device__ float4 g_hw4[(size_t)NN * HH / 4];   // GEMM output (message source)
__device__ float4 g_h4 [(size_t)NN * HH / 4];   // hidden state (layer 1)
__device__ float4 g_h24[(size_t)NN * HH / 4];   // hidden state (layer 2)  [race fix]
__device__ float  g_dinv[NN];                   // deg -> rsqrt(deg)
__device__ int    g_is64;                       // edge_index dtype flag

// ---------------------------------------------------------------------------
// Edge dtype detection (harness may deliver int64 as raw words or int32)
// ---------------------------------------------------------------------------
__global__ void k_detect(const int* ei_raw) {
    if (threadIdx.x == 0 && blockIdx.x == 0) {
        int all0 = 1;
        for (int i = 0; i < 64; i++)
            if (ei_raw[2 * i + 1] != 0) { all0 = 0; break; }
        g_is64 = all0;
    }
}

__device__ __forceinline__ int edge_at(const int* ei_raw, size_t idx) {
    return g_is64 ? ei_raw[2 * idx] : ei_raw[idx];
}

// ---------------------------------------------------------------------------
// Degree / normalization
// ---------------------------------------------------------------------------
__global__ void k_deg_init() {
    int i = blockIdx.x * blockDim.x + threadIdx.x;
    if (i < NN) g_dinv[i] = 1.0f;
}

__global__ void k_deg_count(const int* ei_raw) {
    int e = blockIdx.x * blockDim.x + threadIdx.x;
    if (e >= NE) return;
    int d = edge_at(ei_raw, (size_t)NE + e);
    if (d >= 0 && d < NN) atomicAdd(&g_dinv[d], 1.0f);
}

__global__ void k_dinv() {
    int i = blockIdx.x * blockDim.x + threadIdx.x;
    if (i < NN) g_dinv[i] = rsqrtf(g_dinv[i]);
}

// ---------------------------------------------------------------------------
// Split-bf16 tensor GEMM: C = op(A) @ B, ~2^-17 accuracy.
// x = hi + lo (bf16 each); acc += lo*hi' + hi*lo' + hi*hi' (fp32 accum).
// mma.sync.m16n8k16.bf16. BM=128, BN=64, BK=16, 256 thr (8 warps 4m x 2n).
// A_SRC: 0 ext / 1 g_h / 2 g_h2.  C_DST: 0 ext / 1 g_hw.
// FUSE (H_DST): 0 none / 1 write g_h / 2 write g_h2  (h = bias + dinv^2 * C).
// NOTE: H_DST buffer must differ from A_SRC buffer (no read/write overlap).
// ---------------------------------------------------------------------------
__device__ __forceinline__ void split2(float a, float b, unsigned& hi, unsigned& lo) {
    __nv_bfloat16 ha = __float2bfloat16(a);
    __nv_bfloat16 hb = __float2bfloat16(b);
    __nv_bfloat16 la = __float2bfloat16(a - __bfloat162float(ha));
    __nv_bfloat16 lb = __float2bfloat16(b - __bfloat162float(hb));
    hi = (unsigned)__bfloat16_as_ushort(ha) | ((unsigned)__bfloat16_as_ushort(hb) << 16);
    lo = (unsigned)__bfloat16_as_ushort(la) | ((unsigned)__bfloat16_as_ushort(lb) << 16);
}

template<bool RELU_A, int A_SRC, int C_DST, int H_DST>
__global__ void k_mma_gemm(const float* Aext, const float* B, float* Cext,
                           const float* bias, int M, int Kc, int Nc) {
    const float* A = (A_SRC == 1) ? (const float*)g_h4
                   : (A_SRC == 2) ? (const float*)g_h24 : Aext;
    float*       C = (C_DST == 1) ? (float*)g_hw4       : Cext;
    float*       Hd = (H_DST == 1) ? (float*)g_h4
                    : (H_DST == 2) ? (float*)g_h24      : nullptr;

    const int BM = 128, BN = 64, BK = 16;
    __shared__ unsigned AsH[BM][BK / 2 + 1], AsL[BM][BK / 2 + 1];
    __shared__ unsigned BsH[BK / 2][BN + 1], BsL[BK / 2][BN + 1];

    int tid  = threadIdx.x;
    int wid  = tid >> 5;
    int lane = tid & 31;
    int wm   = wid >> 1;           // 0..3  (m warp)
    int wn   = wid & 1;            // 0..1  (n warp)
    int brow = blockIdx.y * BM;
    int bcol = blockIdx.x * BN;

    float acc[2][4][4];
    #pragma unroll
    for (int i = 0; i < 2; i++)
        #pragma unroll
        for (int j = 0; j < 4; j++)
            #pragma unroll
            for (int r = 0; r < 4; r++) acc[i][j][r] = 0.0f;

    for (int k0 = 0; k0 < Kc; k0 += BK) {
        // A tile: 128x16 floats = 512 float4, 2 per thread; pack k-pairs
        #pragma unroll
        for (int l = 0; l < 2; l++) {
            int f  = tid + l * 256;
            int ar = f >> 2;              // 0..127
            int ak = (f & 3) << 2;        // 0,4,8,12
            int gr = brow + ar;
            float4 v = make_float4(0.f, 0.f, 0.f, 0.f);
            if (gr < M) v = *(const float4*)(A + (size_t)gr * Kc + k0 + ak);
            if (RELU_A) {
                v.x = fmaxf(v.x, 0.f); v.y = fmaxf(v.y, 0.f);
                v.z = fmaxf(v.z, 0.f); v.w = fmaxf(v.w, 0.f);
            }
            int k2 = ak >> 1;             // 0,2,4,6
            split2(v.x, v.y, AsH[ar][k2    ], AsL[ar][k2    ]);
            split2(v.z, v.w, AsH[ar][k2 + 1], AsL[ar][k2 + 1]);
        }
        // B tile: 16x64 floats; threads 0..127 load 2 rows x 4 cols (k-pairs)
        if (tid < 128) {
            int r2 = tid >> 4;            // 0..7
            int bc = (tid & 15) << 2;     // 0..60
            float4 v0 = *(const float4*)(B + (size_t)(k0 + 2 * r2    ) * Nc + bcol + bc);
            float4 v1 = *(const float4*)(B + (size_t)(k0 + 2 * r2 + 1) * Nc + bcol + bc);
            split2(v0.x, v1.x, BsH[r2][bc + 0], BsL[r2][bc + 0]);
            split2(v0.y, v1.y, BsH[r2][bc + 1], BsL[r2][bc + 1]);
            split2(v0.z, v1.z, BsH[r2][bc + 2], BsL[r2][bc + 2]);
            split2(v0.w, v1.w, BsH[r2][bc + 3], BsL[r2][bc + 3]);
        }
        __syncthreads();

        {
            int t = lane & 3;             // k2 base
            int g = lane >> 2;            // group row/col
            unsigned ah[2][4], al[2][4];
            #pragma unroll
            for (int fm = 0; fm < 2; fm++) {
                int r0 = wm * 32 + fm * 16 + g;
                ah[fm][0] = AsH[r0    ][t    ];
                ah[fm][1] = AsH[r0 + 8][t    ];
                ah[fm][2] = AsH[r0    ][t + 4];
                ah[fm][3] = AsH[r0 + 8][t + 4];
                al[fm][0] = AsL[r0    ][t    ];
                al[fm][1] = AsL[r0 + 8][t    ];
                al[fm][2] = AsL[r0    ][t + 4];
                al[fm][3] = AsL[r0 + 8][t + 4];
            }
            unsigned bh[4][2], bl[4][2];
            #pragma unroll
            for (int fn = 0; fn < 4; fn++) {
                int cc = wn * 32 + fn * 8 + g;
                bh[fn][0] = BsH[t    ][cc];
                bh[fn][1] = BsH[t + 4][cc];
                bl[fn][0] = BsL[t    ][cc];
                bl[fn][1] = BsL[t + 4][cc];
            }
            #pragma unroll
            for (int fm = 0; fm < 2; fm++)
                #pragma unroll
                for (int fn = 0; fn < 4; fn++) {
                    float* d = acc[fm][fn];
                    asm volatile(
                        "mma.sync.aligned.m16n8k16.row.col.f32.bf16.bf16.f32 "
                        "{%0,%1,%2,%3}, {%4,%5,%6,%7}, {%8,%9}, {%0,%1,%2,%3};"
                        : "+f"(d[0]), "+f"(d[1]), "+f"(d[2]), "+f"(d[3])
                        : "r"(al[fm][0]), "r"(al[fm][1]), "r"(al[fm][2]), "r"(al[fm][3]),
                          "r"(bh[fn][0]), "r"(bh[fn][1]));
                    asm volatile(
                        "mma.sync.aligned.m16n8k16.row.col.f32.bf16.bf16.f32 "
                        "{%0,%1,%2,%3}, {%4,%5,%6,%7}, {%8,%9}, {%0,%1,%2,%3};"
                        : "+f"(d[0]), "+f"(d[1]), "+f"(d[2]), "+f"(d[3])
                        : "r"(ah[fm][0]), "r"(ah[fm][1]), "r"(ah[fm][2]), "r"(ah[fm][3]),
                          "r"(bl[fn][0]), "r"(bl[fn][1]));
                    asm volatile(
                        "mma.sync.aligned.m16n8k16.row.col.f32.bf16.bf16.f32 "
                        "{%0,%1,%2,%3}, {%4,%5,%6,%7}, {%8,%9}, {%0,%1,%2,%3};"
                        : "+f"(d[0]), "+f"(d[1]), "+f"(d[2]), "+f"(d[3])
                        : "r"(ah[fm][0]), "r"(ah[fm][1]), "r"(ah[fm][2]), "r"(ah[fm][3]),
                          "r"(bh[fn][0]), "r"(bh[fn][1]));
                }
        }
        __syncthreads();
    }

    // Epilogue
    #pragma unroll
    for (int fm = 0; fm < 2; fm++) {
        int row0 = brow + wm * 32 + fm * 16 + (lane >> 2);
        #pragma unroll
        for (int half = 0; half < 2; half++) {
            int row = row0 + half * 8;
            if (row >= M) continue;
            float w = 0.0f;
            if (H_DST != 0) { float di = g_dinv[row]; w = di * di; }
            #pragma unroll
            for (int fn = 0; fn < 4; fn++) {
                int col = bcol + wn * 32 + fn * 8 + 2 * (lane & 3);
                float v0 = acc[fm][fn][half * 2 + 0];
                float v1 = acc[fm][fn][half * 2 + 1];
                *(float2*)(C + (size_t)row * Nc + col) = make_float2(v0, v1);
                if (H_DST != 0) {
                    float h0 = fmaf(w, v0, bias[col]);
                    float h1 = fmaf(w, v1, bias[col + 1]);
                    *(float2*)(Hd + (size_t)row * Nc + col) = make_float2(h0, h1);
                }
            }
        }
    }
}

// ---------------------------------------------------------------------------
// Edge scatter: one warp per edge, h_dst[dst] += norm * g_hw[src]
// DST: 1 = g_h, 2 = g_h2
// ---------------------------------------------------------------------------
template<int DST>
__global__ void k_agg_edge(const int* ei_raw) {
    int gtid = blockIdx.x * blockDim.x + threadIdx.x;
    int e    = gtid >> 5;
    int lane = gtid & 31;
    if (e >= NE) return;
    int s = edge_at(ei_raw, (size_t)e);
    int d = edge_at(ei_raw, (size_t)NE + e);
    if ((unsigned)s >= NN || (unsigned)d >= NN) return;
    float w = g_dinv[s] * g_dinv[d];
    const float4* hs4 = g_hw4 + (size_t)s * (HH / 4);
    float* od = ((DST == 1) ? (float*)g_h4 : (float*)g_h24) + (size_t)d * HH;
    #pragma unroll
    for (int jj = 0; jj < 2; jj++) {
        int j4 = lane + jj * 32;
        float4 v = hs4[j4];
        int j = j4 * 4;
        atomicAdd(od + j + 0, w * v.x);
        atomicAdd(od + j + 1, w * v.y);
        atomicAdd(od + j + 2, w * v.z);
        atomicAdd(od + j + 3, w * v.w);
    }
}

// ---------------------------------------------------------------------------
// Softmax over K=64, warp per row. d_out layout: [S | logits], each NN*KK.
// ---------------------------------------------------------------------------
__global__ void k_softmax(const float* log_tau, float* out) {
    int gtid = blockIdx.x * blockDim.x + threadIdx.x;
    int row  = gtid >> 5;
    int lane = gtid & 31;
    if (row >= NN) return;
    const float* lg = out + (size_t)NN * KK + (size_t)row * KK;
    float inv_tau = __expf(-log_tau[0]);
    float a = lg[lane] * inv_tau;
    float b = lg[lane + 32] * inv_tau;
    float m = fmaxf(a, b);
    #pragma unroll
    for (int off = 16; off > 0; off >>= 1)
        m = fmaxf(m, __shfl_xor_sync(0xFFFFFFFFu, m, off));
    float e0 = __expf(a - m);
    float e1 = __expf(b - m);
    float s = e0 + e1;
    #pragma unroll
    for (int off = 16; off > 0; off >>= 1)
        s += __shfl_xor_sync(0xFFFFFFFFu, s, off);
    float inv = 1.0f / s;
    float* S = out + (size_t)row * KK;
    S[lane]      = e0 * inv;
    S[lane + 32] = e1 * inv;
}

// ---------------------------------------------------------------------------
extern "C" void kernel_launch(void* const* d_in, const int* in_sizes, int n_in,
                              void* d_out, int out_size) {
    const float* x       = (const float*)d_in[0];
    const int*   ei_raw  = (const int*)d_in[1];
    const float* W1      = (const float*)d_in[2];
    const float* b1      = (const float*)d_in[3];
    const float* W2      = (const float*)d_in[4];
    const float* b2      = (const float*)d_in[5];
    const float* Wk      = (const float*)d_in[6];
    const float* log_tau = (const float*)d_in[7];
    float* out = (float*)d_out;

    k_detect   <<<1, 32>>>(ei_raw);
    k_deg_init <<<(NN + 255) / 256, 256>>>();
    k_deg_count<<<(NE + 255) / 256, 256>>>(ei_raw);
    k_dinv     <<<(NN + 255) / 256, 256>>>();

    dim3 grid_H(HH / 64, (NN + 127) / 128);
    dim3 grid_K(KK / 64, (NN + 127) / 128);

    // Layer 1: g_hw = x @ W1, fused g_h = b1 + dinv^2*hw ; scatter into g_h
    k_mma_gemm<false, 0, 1, 1><<<grid_H, 256>>>(x, W1, nullptr, b1, NN, DD, HH);
    k_agg_edge<1><<<NE / 8, 256>>>(ei_raw);

    // Layer 2: g_hw = relu(g_h) @ W2, fused g_h2 = b2 + dinv^2*hw ; scatter into g_h2
    // (reads g_h, writes g_h2 -> no read/write race)
    k_mma_gemm<true, 1, 1, 2><<<grid_H, 256>>>(nullptr, W2, nullptr, b2, NN, HH, HH);
    k_agg_edge<2><<<NE / 8, 256>>>(ei_raw);

    // Head: logits = g_h2 @ Wk ; softmax
    float* logits = out + (size_t)NN * KK;
    k_mma_gemm<false, 2, 0, 0><<<grid_K, 256>>>(nullptr, Wk, logits, nullptr, NN, HH, KK);
    k_softmax<<<(NN + 7) / 8, 256>>>(log_tau, out);
}

// round 10
// speedup vs baseline: 2.6858x; 2.4625x over previous
#include <cuda_runtime.h>
#include <cuda_bf16.h>
#include <math.h>

#define NN 100000
#define NE 1600000
#define DD 512
#define HH 256
#define KK 64
#define SCAN_B 256
#define SCAN_NB ((NN + SCAN_B - 1) / SCAN_B)   // 391

// Scratch: __device__ globals, referenced ONLY from device code.
__device__ float4 g_hw4[(size_t)NN * HH / 4];   // GEMM output (message source)
__device__ float4 g_h4 [(size_t)NN * HH / 4];   // hidden state (layer 1)
__device__ float4 g_h24[(size_t)NN * HH / 4];   // hidden state (layer 2)
__device__ float  g_dinv[NN];                   // rsqrt(deg)
__device__ int    g_deg[NN];                    // in-degree (excl self)
__device__ int    g_off[NN + 1];                // CSR row offsets (by dst)
__device__ int    g_cur[NN];                    // fill cursors
__device__ int    g_csr[NE];                    // CSR src indices
__device__ int    g_blocksum[SCAN_NB];          // scan partials
__device__ int    g_is64;                       // edge_index dtype flag

// ---------------------------------------------------------------------------
// Edge dtype detection
// ---------------------------------------------------------------------------
__global__ void k_detect(const int* ei_raw) {
    if (threadIdx.x == 0 && blockIdx.x == 0) {
        int all0 = 1;
        for (int i = 0; i < 64; i++)
            if (ei_raw[2 * i + 1] != 0) { all0 = 0; break; }
        g_is64 = all0;
    }
}

__device__ __forceinline__ int edge_at(const int* ei_raw, size_t idx) {
    return g_is64 ? ei_raw[2 * idx] : ei_raw[idx];
}

// ---------------------------------------------------------------------------
// CSR build: degree count -> scan -> fill. Also dinv = rsqrt(deg+1).
// ---------------------------------------------------------------------------
__global__ void k_zero() {
    int i = blockIdx.x * blockDim.x + threadIdx.x;
    if (i < NN) { g_deg[i] = 0; g_cur[i] = 0; }
}

__global__ void k_deg_count(const int* ei_raw) {
    int e = blockIdx.x * blockDim.x + threadIdx.x;
    if (e >= NE) return;
    int d = edge_at(ei_raw, (size_t)NE + e);
    if (d >= 0 && d < NN) atomicAdd(&g_deg[d], 1);
}

__global__ void k_dinv() {
    int i = blockIdx.x * blockDim.x + threadIdx.x;
    if (i < NN) g_dinv[i] = rsqrtf((float)(g_deg[i] + 1));
}

// scan kernel A: per-block reduce of degrees
__global__ void k_scan_reduce() {
    __shared__ int sh[SCAN_B];
    int i = blockIdx.x * SCAN_B + threadIdx.x;
    sh[threadIdx.x] = (i < NN) ? g_deg[i] : 0;
    __syncthreads();
    for (int s = SCAN_B / 2; s > 0; s >>= 1) {
        if (threadIdx.x < s) sh[threadIdx.x] += sh[threadIdx.x + s];
        __syncthreads();
    }
    if (threadIdx.x == 0) g_blocksum[blockIdx.x] = sh[0];
}

// scan kernel B: serial scan of block sums (391 elems, 1 thread) -> bases
__global__ void k_scan_bases() {
    if (threadIdx.x == 0 && blockIdx.x == 0) {
        int run = 0;
        for (int b = 0; b < SCAN_NB; b++) {
            int v = g_blocksum[b];
            g_blocksum[b] = run;
            run += v;
        }
        g_off[NN] = run;   // == NE
    }
}

// scan kernel C: per-block exclusive scan + base -> g_off
__global__ void k_scan_offsets() {
    __shared__ int sh[SCAN_B];
    int i = blockIdx.x * SCAN_B + threadIdx.x;
    int v = (i < NN) ? g_deg[i] : 0;
    sh[threadIdx.x] = v;
    __syncthreads();
    // Hillis-Steele inclusive
    for (int s = 1; s < SCAN_B; s <<= 1) {
        int t = (threadIdx.x >= s) ? sh[threadIdx.x - s] : 0;
        __syncthreads();
        sh[threadIdx.x] += t;
        __syncthreads();
    }
    if (i < NN) g_off[i] = g_blocksum[blockIdx.x] + sh[threadIdx.x] - v;  // exclusive
}

__global__ void k_fill(const int* ei_raw) {
    int e = blockIdx.x * blockDim.x + threadIdx.x;
    if (e >= NE) return;
    int s = edge_at(ei_raw, (size_t)e);
    int d = edge_at(ei_raw, (size_t)NE + e);
    if ((unsigned)s >= NN || (unsigned)d >= NN) return;
    int pos = g_off[d] + atomicAdd(&g_cur[d], 1);
    g_csr[pos] = s;
}

// ---------------------------------------------------------------------------
// Split-bf16 tensor GEMM: C = op(A) @ B, ~2^-17 accuracy.
// mma.sync.m16n8k16.bf16. BM=128, BN=64, BK=16, 256 thr (8 warps 4m x 2n).
// A_SRC: 0 ext / 1 g_h / 2 g_h2.  C_DST: 0 ext / 1 g_hw.
// ---------------------------------------------------------------------------
__device__ __forceinline__ void split2(float a, float b, unsigned& hi, unsigned& lo) {
    __nv_bfloat16 ha = __float2bfloat16(a);
    __nv_bfloat16 hb = __float2bfloat16(b);
    __nv_bfloat16 la = __float2bfloat16(a - __bfloat162float(ha));
    __nv_bfloat16 lb = __float2bfloat16(b - __bfloat162float(hb));
    hi = (unsigned)__bfloat16_as_ushort(ha) | ((unsigned)__bfloat16_as_ushort(hb) << 16);
    lo = (unsigned)__bfloat16_as_ushort(la) | ((unsigned)__bfloat16_as_ushort(lb) << 16);
}

template<bool RELU_A, int A_SRC, int C_DST>
__global__ void k_mma_gemm(const float* Aext, const float* B, float* Cext,
                           int M, int Kc, int Nc) {
    const float* A = (A_SRC == 1) ? (const float*)g_h4
                   : (A_SRC == 2) ? (const float*)g_h24 : Aext;
    float*       C = (C_DST == 1) ? (float*)g_hw4       : Cext;

    const int BM = 128, BN = 64, BK = 16;
    __shared__ unsigned AsH[BM][BK / 2 + 1], AsL[BM][BK / 2 + 1];
    __shared__ unsigned BsH[BK / 2][BN + 1], BsL[BK / 2][BN + 1];

    int tid  = threadIdx.x;
    int wid  = tid >> 5;
    int lane = tid & 31;
    int wm   = wid >> 1;
    int wn   = wid & 1;
    int brow = blockIdx.y * BM;
    int bcol = blockIdx.x * BN;

    float acc[2][4][4];
    #pragma unroll
    for (int i = 0; i < 2; i++)
        #pragma unroll
        for (int j = 0; j < 4; j++)
            #pragma unroll
            for (int r = 0; r < 4; r++) acc[i][j][r] = 0.0f;

    for (int k0 = 0; k0 < Kc; k0 += BK) {
        #pragma unroll
        for (int l = 0; l < 2; l++) {
            int f  = tid + l * 256;
            int ar = f >> 2;
            int ak = (f & 3) << 2;
            int gr = brow + ar;
            float4 v = make_float4(0.f, 0.f, 0.f, 0.f);
            if (gr < M) v = *(const float4*)(A + (size_t)gr * Kc + k0 + ak);
            if (RELU_A) {
                v.x = fmaxf(v.x, 0.f); v.y = fmaxf(v.y, 0.f);
                v.z = fmaxf(v.z, 0.f); v.w = fmaxf(v.w, 0.f);
            }
            int k2 = ak >> 1;
            split2(v.x, v.y, AsH[ar][k2    ], AsL[ar][k2    ]);
            split2(v.z, v.w, AsH[ar][k2 + 1], AsL[ar][k2 + 1]);
        }
        if (tid < 128) {
            int r2 = tid >> 4;
            int bc = (tid & 15) << 2;
            float4 v0 = *(const float4*)(B + (size_t)(k0 + 2 * r2    ) * Nc + bcol + bc);
            float4 v1 = *(const float4*)(B + (size_t)(k0 + 2 * r2 + 1) * Nc + bcol + bc);
            split2(v0.x, v1.x, BsH[r2][bc + 0], BsL[r2][bc + 0]);
            split2(v0.y, v1.y, BsH[r2][bc + 1], BsL[r2][bc + 1]);
            split2(v0.z, v1.z, BsH[r2][bc + 2], BsL[r2][bc + 2]);
            split2(v0.w, v1.w, BsH[r2][bc + 3], BsL[r2][bc + 3]);
        }
        __syncthreads();

        {
            int t = lane & 3;
            int g = lane >> 2;
            unsigned ah[2][4], al[2][4];
            #pragma unroll
            for (int fm = 0; fm < 2; fm++) {
                int r0 = wm * 32 + fm * 16 + g;
                ah[fm][0] = AsH[r0    ][t    ];
                ah[fm][1] = AsH[r0 + 8][t    ];
                ah[fm][2] = AsH[r0    ][t + 4];
                ah[fm][3] = AsH[r0 + 8][t + 4];
                al[fm][0] = AsL[r0    ][t    ];
                al[fm][1] = AsL[r0 + 8][t    ];
                al[fm][2] = AsL[r0    ][t + 4];
                al[fm][3] = AsL[r0 + 8][t + 4];
            }
            unsigned bh[4][2], bl[4][2];
            #pragma unroll
            for (int fn = 0; fn < 4; fn++) {
                int cc = wn * 32 + fn * 8 + g;
                bh[fn][0] = BsH[t    ][cc];
                bh[fn][1] = BsH[t + 4][cc];
                bl[fn][0] = BsL[t    ][cc];
                bl[fn][1] = BsL[t + 4][cc];
            }
            #pragma unroll
            for (int fm = 0; fm < 2; fm++)
                #pragma unroll
                for (int fn = 0; fn < 4; fn++) {
                    float* d = acc[fm][fn];
                    asm volatile(
                        "mma.sync.aligned.m16n8k16.row.col.f32.bf16.bf16.f32 "
                        "{%0,%1,%2,%3}, {%4,%5,%6,%7}, {%8,%9}, {%0,%1,%2,%3};"
                        : "+f"(d[0]), "+f"(d[1]), "+f"(d[2]), "+f"(d[3])
                        : "r"(al[fm][0]), "r"(al[fm][1]), "r"(al[fm][2]), "r"(al[fm][3]),
                          "r"(bh[fn][0]), "r"(bh[fn][1]));
                    asm volatile(
                        "mma.sync.aligned.m16n8k16.row.col.f32.bf16.bf16.f32 "
                        "{%0,%1,%2,%3}, {%4,%5,%6,%7}, {%8,%9}, {%0,%1,%2,%3};"
                        : "+f"(d[0]), "+f"(d[1]), "+f"(d[2]), "+f"(d[3])
                        : "r"(ah[fm][0]), "r"(ah[fm][1]), "r"(ah[fm][2]), "r"(ah[fm][3]),
                          "r"(bl[fn][0]), "r"(bl[fn][1]));
                    asm volatile(
                        "mma.sync.aligned.m16n8k16.row.col.f32.bf16.bf16.f32 "
                        "{%0,%1,%2,%3}, {%4,%5,%6,%7}, {%8,%9}, {%0,%1,%2,%3};"
                        : "+f"(d[0]), "+f"(d[1]), "+f"(d[2]), "+f"(d[3])
                        : "r"(ah[fm][0]), "r"(ah[fm][1]), "r"(ah[fm][2]), "r"(ah[fm][3]),
                          "r"(bh[fn][0]), "r"(bh[fn][1]));
                }
        }
        __syncthreads();
    }

    #pragma unroll
    for (int fm = 0; fm < 2; fm++) {
        int row0 = brow + wm * 32 + fm * 16 + (lane >> 2);
        #pragma unroll
        for (int half = 0; half < 2; half++) {
            int row = row0 + half * 8;
            if (row >= M) continue;
            #pragma unroll
            for (int fn = 0; fn < 4; fn++) {
                int col = bcol + wn * 32 + fn * 8 + 2 * (lane & 3);
                *(float2*)(C + (size_t)row * Nc + col) =
                    make_float2(acc[fm][fn][half * 2 + 0], acc[fm][fn][half * 2 + 1]);
            }
        }
    }
}

// ---------------------------------------------------------------------------
// CSR gather aggregation: warp per node, no atomics.
// out[node] = bias + dinv^2 * hw[node] + sum_in (dinv[n]*dinv[s]) * hw[s]
// DST: 1 = g_h, 2 = g_h2
// ---------------------------------------------------------------------------
template<int DST>
__global__ void k_agg_gather(const float* bias) {
    int gtid = blockIdx.x * blockDim.x + threadIdx.x;
    int node = gtid >> 5;
    int lane = gtid & 31;
    if (node >= NN) return;

    float di = g_dinv[node];
    float ws = di * di;
    const float4* hw = g_hw4 + (size_t)node * (HH / 4);
    float4 b0 = ((const float4*)bias)[lane];
    float4 b1 = ((const float4*)bias)[lane + 32];
    float4 v0 = hw[lane];
    float4 v1 = hw[lane + 32];
    float4 a0 = make_float4(fmaf(ws, v0.x, b0.x), fmaf(ws, v0.y, b0.y),
                            fmaf(ws, v0.z, b0.z), fmaf(ws, v0.w, b0.w));
    float4 a1 = make_float4(fmaf(ws, v1.x, b1.x), fmaf(ws, v1.y, b1.y),
                            fmaf(ws, v1.z, b1.z), fmaf(ws, v1.w, b1.w));

    int e0 = g_off[node], e1 = g_off[node + 1];
    for (int i = e0; i < e1; i++) {
        int s = g_csr[i];                       // broadcast load
        float w = di * g_dinv[s];
        const float4* hs = g_hw4 + (size_t)s * (HH / 4);
        float4 u0 = hs[lane];
        float4 u1 = hs[lane + 32];
        a0.x = fmaf(w, u0.x, a0.x); a0.y = fmaf(w, u0.y, a0.y);
        a0.z = fmaf(w, u0.z, a0.z); a0.w = fmaf(w, u0.w, a0.w);
        a1.x = fmaf(w, u1.x, a1.x); a1.y = fmaf(w, u1.y, a1.y);
        a1.z = fmaf(w, u1.z, a1.z); a1.w = fmaf(w, u1.w, a1.w);
    }

    float4* out = ((DST == 1) ? g_h4 : g_h24) + (size_t)node * (HH / 4);
    out[lane]      = a0;
    out[lane + 32] = a1;
}

// ---------------------------------------------------------------------------
// Softmax over K=64, warp per row. d_out layout: [S | logits], each NN*KK.
// ---------------------------------------------------------------------------
__global__ void k_softmax(const float* log_tau, float* out) {
    int gtid = blockIdx.x * blockDim.x + threadIdx.x;
    int row  = gtid >> 5;
    int lane = gtid & 31;
    if (row >= NN) return;
    const float* lg = out + (size_t)NN * KK + (size_t)row * KK;
    float inv_tau = __expf(-log_tau[0]);
    float a = lg[lane] * inv_tau;
    float b = lg[lane + 32] * inv_tau;
    float m = fmaxf(a, b);
    #pragma unroll
    for (int off = 16; off > 0; off >>= 1)
        m = fmaxf(m, __shfl_xor_sync(0xFFFFFFFFu, m, off));
    float e0 = __expf(a - m);
    float e1 = __expf(b - m);
    float s = e0 + e1;
    #pragma unroll
    for (int off = 16; off > 0; off >>= 1)
        s += __shfl_xor_sync(0xFFFFFFFFu, s, off);
    float inv = 1.0f / s;
    float* S = out + (size_t)row * KK;
    S[lane]      = e0 * inv;
    S[lane + 32] = e1 * inv;
}

// ---------------------------------------------------------------------------
extern "C" void kernel_launch(void* const* d_in, const int* in_sizes, int n_in,
                              void* d_out, int out_size) {
    const float* x       = (const float*)d_in[0];
    const int*   ei_raw  = (const int*)d_in[1];
    const float* W1      = (const float*)d_in[2];
    const float* b1      = (const float*)d_in[3];
    const float* W2      = (const float*)d_in[4];
    const float* b2      = (const float*)d_in[5];
    const float* Wk      = (const float*)d_in[6];
    const float* log_tau = (const float*)d_in[7];
    float* out = (float*)d_out;

    // CSR build + norms
    k_detect      <<<1, 32>>>(ei_raw);
    k_zero        <<<(NN + 255) / 256, 256>>>();
    k_deg_count   <<<(NE + 255) / 256, 256>>>(ei_raw);
    k_dinv        <<<(NN + 255) / 256, 256>>>();
    k_scan_reduce <<<SCAN_NB, SCAN_B>>>();
    k_scan_bases  <<<1, 32>>>();
    k_scan_offsets<<<SCAN_NB, SCAN_B>>>();
    k_fill        <<<(NE + 255) / 256, 256>>>(ei_raw);

    dim3 grid_H(HH / 64, (NN + 127) / 128);
    dim3 grid_K(KK / 64, (NN + 127) / 128);
    int agg_blocks = (NN * 32 + 255) / 256;

    // Layer 1
    k_mma_gemm<false, 0, 1><<<grid_H, 256>>>(x, W1, nullptr, NN, DD, HH);
    k_agg_gather<1><<<agg_blocks, 256>>>(b1);

    // Layer 2
    k_mma_gemm<true, 1, 1><<<grid_H, 256>>>(nullptr, W2, nullptr, NN, HH, HH);
    k_agg_gather<2><<<agg_blocks, 256>>>(b2);

    // Head
    float* logits = out + (size_t)NN * KK;
    k_mma_gemm<false, 2, 0><<<grid_K, 256>>>(nullptr, Wk, logits, NN, HH, KK);
    k_softmax<<<(NN + 7) / 8, 256>>>(log_tau, out);
}